// round 16
// baseline (speedup 1.0000x reference)
#include <cuda_runtime.h>
#include <cuda_fp16.h>
#include <cstdint>

#define BB 4
#define LL 1024
#define DD 768
#define HH 12
#define DHH 64

// Packed fp16 scratch: XM tiles, k-contiguous, k-chunks of 64.
//   128-row tile = 128 x 72 halfs (64 data + 8 pad) = 18432B
//   64-row tile  =  64 x 72 halfs = 9216B
#define TH128 9216
#define TH64  4608
__device__ __align__(1024) __half g_xp [(size_t)BB * 8 * 12 * TH128];
__device__ __align__(1024) __half g_qp [(size_t)HH * 6 * 12 * TH128];
__device__ __align__(1024) __half g_kp [(size_t)HH * 6 * 12 * TH128];
__device__ __align__(1024) __half g_vp [(size_t)HH * 12 * TH64];
__device__ __align__(1024) __half g_Mp [(size_t)HH * 6 * 12 * TH128];
__device__ __align__(1024) __half g_Ap [(size_t)BB * HH * 8 * 12 * TH128];
__device__ __align__(1024) __half g_Sp [(size_t)BB * HH * 8 * 16 * TH128]; // P = exp(S)
__device__ __align__(1024) __half g_Vtp[(size_t)BB * HH * 16 * TH64];
__device__ float g_rsum[(size_t)BB * HH * LL];       // per-row sums of exp(S)
__device__ int   g_cnt[(size_t)BB * HH * 8];         // per (z, l-tile) completion count

__device__ __forceinline__ void mma_f16(float* c, const unsigned* a, const unsigned* b) {
    asm volatile(
        "mma.sync.aligned.m16n8k16.row.col.f32.f16.f16.f32 "
        "{%0,%1,%2,%3}, {%4,%5,%6,%7}, {%8,%9}, {%0,%1,%2,%3};"
        : "+f"(c[0]), "+f"(c[1]), "+f"(c[2]), "+f"(c[3])
        : "r"(a[0]), "r"(a[1]), "r"(a[2]), "r"(a[3]), "r"(b[0]), "r"(b[1]));
}

__device__ __forceinline__ uint32_t sa32(const void* p) {
    return (uint32_t)__cvta_generic_to_shared(p);
}
__device__ __forceinline__ void bulk_g2s(uint32_t dst, const void* src,
                                         uint32_t bytes, uint32_t mbar) {
    asm volatile(
        "cp.async.bulk.shared::cluster.global.mbarrier::complete_tx::bytes [%0], [%1], %2, [%3];"
        :: "r"(dst), "l"(src), "r"(bytes), "r"(mbar) : "memory");
}
__device__ __forceinline__ void bar_wait(uint32_t mbar, unsigned parity) {
    asm volatile(
        "{\n\t.reg .pred P;\n\t"
        "W_%=:\n\t"
        "mbarrier.try_wait.parity.acquire.cta.shared::cta.b64 P, [%0], %1, 0x989680;\n\t"
        "@P bra D_%=;\n\t"
        "bra W_%=;\n\t"
        "D_%=:\n\t}"
        :: "r"(mbar), "r"(parity) : "memory");
}
#define MBAR_INIT(a, c) \
    asm volatile("mbarrier.init.shared.b64 [%0], %1;" :: "r"(a), "r"(c) : "memory")
#define MBAR_TX(a, b) \
    asm volatile("mbarrier.arrive.expect_tx.shared.b64 _, [%0], %1;" :: "r"(a), "r"(b) : "memory")
#define MBAR_ARRIVE(a) \
    asm volatile("mbarrier.arrive.release.cta.shared::cta.b64 _, [%0];" :: "r"(a) : "memory")

// ---------------------------------------------------------------------------
// Generic bulk-fed fp16 HMMA GEMM body (G1, G2, G5).
//  C[m,n] = sum_k A[m,k]*B[n,k].  Block 128 x BROWS x 64, 3-stage ring.
//  EPI: 1 fp16 XM tiles rows=m; 2 fp16 XM tiles rows=n (ETR rows/tile)
// ---------------------------------------------------------------------------
template<int AZ, int BZ, int BROWS, int EPI, int ETR>
__device__ __forceinline__
void gemm_dev(const __half* __restrict__ Apk, const __half* __restrict__ Bpk,
              void* __restrict__ Cg, int nkt, int cNK, long czs,
              int bx, int by, int bz, int gdx, int gdy, __half* smem)
{
    constexpr int BTH = BROWS * 72;
    constexpr uint32_t ABYT = TH128 * 2, BBYT = BTH * 2;
    constexpr int STAGE = TH128 + BTH;
    constexpr int NT = BROWS / 32;

    const uint32_t mb0 = sa32(&smem[0]);
    __half* tiles = smem + 512;

    const int z = bz;
    const long zA = (AZ == 1) ? z / HH : (AZ == 2 ? z % HH : z);
    const long zB = (BZ == 1) ? z / HH : (BZ == 2 ? z % HH : z);
    const __half* Abase = Apk + ((zA * gdy + by) * (long)nkt) * TH128;
    const __half* Bbase = Bpk + ((zB * gdx + bx) * (long)nkt) * BTH;

    const int tid = threadIdx.x;
    const int lane = tid & 31;
    const int wid = tid >> 5;
    const int wm = (wid & 1) * 64;
    const int wn = (wid >> 1) * (BROWS / 4);
    const int lm = lane >> 2;
    const int lk = lane & 3;
    const int m0 = by * 128;
    const int n0 = bx * BROWS;

    float acc[4][NT][4];
    #pragma unroll
    for (int i = 0; i < 4; i++)
        #pragma unroll
        for (int j = 0; j < NT; j++)
            #pragma unroll
            for (int r = 0; r < 4; r++) acc[i][j][r] = 0.f;

    if (tid == 0) {
        MBAR_INIT(mb0, 1);      MBAR_INIT(mb0 + 8, 1);  MBAR_INIT(mb0 + 16, 1);
        MBAR_INIT(mb0 + 24, 8); MBAR_INIT(mb0 + 32, 8); MBAR_INIT(mb0 + 40, 8);
    }
    __syncthreads();

    auto issue = [&](int st, int kt) {
        const uint32_t m = mb0 + 8 * st;
        MBAR_TX(m, ABYT + BBYT);
        bulk_g2s(sa32(tiles) + st * STAGE * 2, Abase + (long)kt * TH128, ABYT, m);
        bulk_g2s(sa32(tiles) + st * STAGE * 2 + ABYT, Bbase + (long)kt * BTH, BBYT, m);
    };
    if (tid == 0) { issue(0, 0); issue(1, 1); issue(2, 2); }

    unsigned phF[3] = {0, 0, 0};
    unsigned phE[3] = {0, 0, 0};
    int st = 0;
    for (int t = 0; t < nkt; t++) {
        bar_wait(mb0 + 8 * st, phF[st]);
        phF[st] ^= 1;
        {
            const __half* __restrict__ Ab = tiles + st * STAGE;
            const __half* __restrict__ Bb = Ab + TH128;
            #pragma unroll
            for (int s = 0; s < 4; s++) {
                const int kb = s * 16 + 2 * lk;
                unsigned a[4][4], b[NT][2];
                #pragma unroll
                for (int mt = 0; mt < 4; mt++) {
                    const int mr = wm + mt * 16 + lm;
                    a[mt][0] = *(const unsigned*)&Ab[mr * 72 + kb];
                    a[mt][1] = *(const unsigned*)&Ab[(mr + 8) * 72 + kb];
                    a[mt][2] = *(const unsigned*)&Ab[mr * 72 + kb + 8];
                    a[mt][3] = *(const unsigned*)&Ab[(mr + 8) * 72 + kb + 8];
                }
                #pragma unroll
                for (int nt = 0; nt < NT; nt++) {
                    const int nc = wn + nt * 8 + lm;
                    b[nt][0] = *(const unsigned*)&Bb[nc * 72 + kb];
                    b[nt][1] = *(const unsigned*)&Bb[nc * 72 + kb + 8];
                }
                #pragma unroll
                for (int mt = 0; mt < 4; mt++)
                    #pragma unroll
                    for (int nt = 0; nt < NT; nt++)
                        mma_f16(acc[mt][nt], a[mt], b[nt]);
            }
        }
        if (lane == 0) MBAR_ARRIVE(mb0 + 24 + 8 * st);
        if (tid == 0 && t + 3 < nkt) {
            bar_wait(mb0 + 24 + 8 * st, phE[st]);
            phE[st] ^= 1;
            issue(st, t + 3);
        }
        st = (st == 2) ? 0 : st + 1;
    }

    #pragma unroll
    for (int mt = 0; mt < 4; mt++) {
        const int rl = wm + mt * 16 + lm;
        const int rg = m0 + rl;
        #pragma unroll
        for (int nt = 0; nt < NT; nt++) {
            const int cl = wn + nt * 8 + 2 * lk;
            const int cg = n0 + cl;
            const float v0 = acc[mt][nt][0], v1 = acc[mt][nt][1];
            const float v2 = acc[mt][nt][2], v3 = acc[mt][nt][3];
            if (EPI == 1) {
                __half* zb = (__half*)Cg + (long)z * czs
                           + ((long)by * cNK + (cg >> 6)) * TH128;
                const int co = cl & 63;
                *(__half2*)&zb[rl * 72 + co]       = __float22half2_rn(make_float2(v0, v1));
                *(__half2*)&zb[(rl + 8) * 72 + co] = __float22half2_rn(make_float2(v2, v3));
            } else {
                __half* zb = (__half*)Cg + (long)z * czs
                           + ((long)(cg / ETR) * cNK + (rg >> 6)) * (ETR * 72);
                const int rr = rg & 63;
                zb[(cg & (ETR - 1)) * 72 + rr]           = __float2half_rn(v0);
                zb[((cg + 1) & (ETR - 1)) * 72 + rr]     = __float2half_rn(v1);
                zb[(cg & (ETR - 1)) * 72 + rr + 8]       = __float2half_rn(v2);
                zb[((cg + 1) & (ETR - 1)) * 72 + rr + 8] = __float2half_rn(v3);
            }
        }
    }
}

template<int AZ, int BZ, int BROWS, int EPI, int ETR>
__global__ __launch_bounds__(256, 2)
void gemm_k(const __half* __restrict__ Apk, const __half* __restrict__ Bpk,
            void* __restrict__ Cg, int nkt, int cNK, long czs)
{
    extern __shared__ __align__(16) __half smem[];
    gemm_dev<AZ, BZ, BROWS, EPI, ETR>(Apk, Bpk, Cg, nkt, cNK, czs,
        blockIdx.x, blockIdx.y, blockIdx.z, gridDim.x, gridDim.y, smem);
}

// ---- fused G1 (M^T = q^T k) + G5 (Vt = x v^T) in one launch ---------------
__global__ __launch_bounds__(256, 2)
void gemm_g1g5(const __half* __restrict__ qp, const __half* __restrict__ kp,
               __half* __restrict__ Mp,
               const __half* __restrict__ xp, const __half* __restrict__ vp,
               __half* __restrict__ Vtp)
{
    extern __shared__ __align__(16) __half smem[];
    const int bid = blockIdx.x;
    if (bid < 432) {                                // G1: grid (6,6,12)
        gemm_dev<0, 0, 128, 2, 128>(qp, kp, Mp, 12, 12, 6L * 12 * TH128,
            bid % 6, (bid / 6) % 6, bid / 36, 6, 6, smem);
    } else {                                        // G5: grid (1,8,48)
        const int t = bid - 432;
        gemm_dev<1, 2, 64, 2, 64>(xp, vp, Vtp, 12, 16, 16L * TH64,
            0, t % 8, t / 8, 1, 8, smem);
    }
}

// ---------------------------------------------------------------------------
// G3 fused with G6: block (bx, by, z) computes P-tile = exp(A x^T) + rsum
// atomics; the LAST of the 8 blocks of panel (z, by) then computes the
// output tile out[z, by-rows] = (P . Vt) / rsum inline.
// ---------------------------------------------------------------------------
__global__ __launch_bounds__(256, 2)
void gemm_g3f(const __half* __restrict__ Apk, const __half* __restrict__ xp,
              __half* __restrict__ Sp, const __half* __restrict__ Vtp,
              float* __restrict__ rsum, float* __restrict__ outv,
              int* __restrict__ cnt)
{
    constexpr int STAGE = 2 * TH128;                // G3 stage (A 128 + B 128 rows)
    constexpr int SG6 = TH128 + TH64;               // G6 stage
    extern __shared__ __align__(16) __half smem[];
    const uint32_t mb0 = sa32(&smem[0]);  // G3: full@0,8,16 empty@24,32,40
                                          // G6: full@48,56,64 empty@72,80,88
    __half* tiles = smem + 512;
    __shared__ int s_old;

    const int bx = blockIdx.x, by = blockIdx.y, z = blockIdx.z;
    const __half* Abase = Apk + ((long)(z * 8 + by) * 12) * TH128;
    const __half* Bbase = xp + (((long)(z / HH) * 8 + bx) * 12) * TH128;

    const int tid = threadIdx.x;
    const int lane = tid & 31;
    const int wid = tid >> 5;
    const int wm = (wid & 1) * 64;
    const int wn = (wid >> 1) * 32;
    const int lm = lane >> 2;
    const int lk = lane & 3;

    float acc[4][4][4];
    #pragma unroll
    for (int i = 0; i < 4; i++)
        #pragma unroll
        for (int j = 0; j < 4; j++)
            #pragma unroll
            for (int r = 0; r < 4; r++) acc[i][j][r] = 0.f;

    if (tid == 0) {
        MBAR_INIT(mb0, 1);      MBAR_INIT(mb0 + 8, 1);  MBAR_INIT(mb0 + 16, 1);
        MBAR_INIT(mb0 + 24, 8); MBAR_INIT(mb0 + 32, 8); MBAR_INIT(mb0 + 40, 8);
        MBAR_INIT(mb0 + 48, 1); MBAR_INIT(mb0 + 56, 1); MBAR_INIT(mb0 + 64, 1);
        MBAR_INIT(mb0 + 72, 8); MBAR_INIT(mb0 + 80, 8); MBAR_INIT(mb0 + 88, 8);
    }
    __syncthreads();

    auto issue = [&](int st, int kt) {
        const uint32_t m = mb0 + 8 * st;
        MBAR_TX(m, 2u * TH128 * 2);
        bulk_g2s(sa32(tiles) + st * STAGE * 2, Abase + (long)kt * TH128, TH128 * 2, m);
        bulk_g2s(sa32(tiles) + st * STAGE * 2 + TH128 * 2, Bbase + (long)kt * TH128,
                 TH128 * 2, m);
    };
    if (tid == 0) { issue(0, 0); issue(1, 1); issue(2, 2); }

    unsigned phF[3] = {0, 0, 0};
    unsigned phE[3] = {0, 0, 0};
    int st = 0;
    for (int t = 0; t < 12; t++) {
        bar_wait(mb0 + 8 * st, phF[st]);
        phF[st] ^= 1;
        {
            const __half* __restrict__ Ab = tiles + st * STAGE;
            const __half* __restrict__ Bb = Ab + TH128;
            #pragma unroll
            for (int s = 0; s < 4; s++) {
                const int kb = s * 16 + 2 * lk;
                unsigned a[4][4], b[4][2];
                #pragma unroll
                for (int mt = 0; mt < 4; mt++) {
                    const int mr = wm + mt * 16 + lm;
                    a[mt][0] = *(const unsigned*)&Ab[mr * 72 + kb];
                    a[mt][1] = *(const unsigned*)&Ab[(mr + 8) * 72 + kb];
                    a[mt][2] = *(const unsigned*)&Ab[mr * 72 + kb + 8];
                    a[mt][3] = *(const unsigned*)&Ab[(mr + 8) * 72 + kb + 8];
                }
                #pragma unroll
                for (int nt = 0; nt < 4; nt++) {
                    const int nc = wn + nt * 8 + lm;
                    b[nt][0] = *(const unsigned*)&Bb[nc * 72 + kb];
                    b[nt][1] = *(const unsigned*)&Bb[nc * 72 + kb + 8];
                }
                #pragma unroll
                for (int mt = 0; mt < 4; mt++)
                    #pragma unroll
                    for (int nt = 0; nt < 4; nt++)
                        mma_f16(acc[mt][nt], a[mt], b[nt]);
            }
        }
        if (lane == 0) MBAR_ARRIVE(mb0 + 24 + 8 * st);
        if (tid == 0 && t + 3 < 12) {
            bar_wait(mb0 + 24 + 8 * st, phE[st]);
            phE[st] ^= 1;
            issue(st, t + 3);
        }
        st = (st == 2) ? 0 : st + 1;
    }

    // ---- P epilogue: exp + store + rsum atomics ----
    #pragma unroll
    for (int mt = 0; mt < 4; mt++) {
        const int rl = wm + mt * 16 + lm;
        const int rg = by * 128 + rl;
        float s0 = 0.f, s1 = 0.f;
        #pragma unroll
        for (int nt = 0; nt < 4; nt++) {
            const int cl = wn + nt * 8 + 2 * lk;
            const int cg = bx * 128 + cl;
            const float e0 = __expf(acc[mt][nt][0]), e1 = __expf(acc[mt][nt][1]);
            const float e2 = __expf(acc[mt][nt][2]), e3 = __expf(acc[mt][nt][3]);
            const __half2 h01 = __float22half2_rn(make_float2(e0, e1));
            const __half2 h23 = __float22half2_rn(make_float2(e2, e3));
            const float2 f01 = __half22float2(h01);
            const float2 f23 = __half22float2(h23);
            s0 += f01.x + f01.y;
            s1 += f23.x + f23.y;
            __half* zb = Sp + (long)z * (128L * TH128)
                       + ((long)by * 16 + (cg >> 6)) * TH128;
            const int co = cl & 63;
            *(__half2*)&zb[rl * 72 + co]       = h01;
            *(__half2*)&zb[(rl + 8) * 72 + co] = h23;
        }
        s0 += __shfl_xor_sync(~0u, s0, 1); s0 += __shfl_xor_sync(~0u, s0, 2);
        s1 += __shfl_xor_sync(~0u, s1, 1); s1 += __shfl_xor_sync(~0u, s1, 2);
        if (lk == 0) {
            atomicAdd(&rsum[(long)z * LL + rg], s0);
            atomicAdd(&rsum[(long)z * LL + rg + 8], s1);
        }
    }

    // ---- completion counter; last block of panel (z, by) runs G6 inline ----
    __syncthreads();
    if (tid == 0) {
        __threadfence();
        s_old = atomicAdd(&cnt[z * 8 + by], 1);
    }
    __syncthreads();
    if (s_old != 7) return;
    __threadfence();

    // ---- inline G6: out[by-rows] = (P . Vt) / rsum, K = 1024 (16 chunks) ----
    const __half* A6 = Sp + (long)z * (128L * TH128) + (long)by * 16 * TH128;
    const __half* B6 = Vtp + (long)z * 16 * TH64;
    const int wn6 = (wid >> 1) * 16;

    float oacc[4][2][4];
    #pragma unroll
    for (int i = 0; i < 4; i++)
        #pragma unroll
        for (int j = 0; j < 2; j++)
            #pragma unroll
            for (int r = 0; r < 4; r++) oacc[i][j][r] = 0.f;

    auto issue6 = [&](int c) {
        const int s6 = c % 3;
        const uint32_t m = mb0 + 48 + 8 * s6;
        MBAR_TX(m, (TH128 + TH64) * 2);
        bulk_g2s(sa32(tiles) + s6 * SG6 * 2, A6 + (long)c * TH128, TH128 * 2, m);
        bulk_g2s(sa32(tiles) + s6 * SG6 * 2 + TH128 * 2, B6 + (long)c * TH64,
                 TH64 * 2, m);
    };
    if (tid == 0) { issue6(0); issue6(1); issue6(2); }

    unsigned pF[3] = {0, 0, 0};
    unsigned pE[3] = {0, 0, 0};
    for (int c = 0; c < 16; c++) {
        const int s6 = c % 3;
        bar_wait(mb0 + 48 + 8 * s6, pF[s6]);
        pF[s6] ^= 1;
        {
            const __half* __restrict__ Ab = tiles + s6 * SG6;
            const __half* __restrict__ Bb = Ab + TH128;
            #pragma unroll
            for (int s = 0; s < 4; s++) {
                const int kb = s * 16 + 2 * lk;
                unsigned a[4][4], b[2][2];
                #pragma unroll
                for (int mt = 0; mt < 4; mt++) {
                    const int mr = wm + mt * 16 + lm;
                    a[mt][0] = *(const unsigned*)&Ab[mr * 72 + kb];
                    a[mt][1] = *(const unsigned*)&Ab[(mr + 8) * 72 + kb];
                    a[mt][2] = *(const unsigned*)&Ab[mr * 72 + kb + 8];
                    a[mt][3] = *(const unsigned*)&Ab[(mr + 8) * 72 + kb + 8];
                }
                #pragma unroll
                for (int nt = 0; nt < 2; nt++) {
                    const int nc = wn6 + nt * 8 + lm;
                    b[nt][0] = *(const unsigned*)&Bb[nc * 72 + kb];
                    b[nt][1] = *(const unsigned*)&Bb[nc * 72 + kb + 8];
                }
                #pragma unroll
                for (int mt = 0; mt < 4; mt++)
                    #pragma unroll
                    for (int nt = 0; nt < 2; nt++)
                        mma_f16(oacc[mt][nt], a[mt], b[nt]);
            }
        }
        if (lane == 0) MBAR_ARRIVE(mb0 + 72 + 8 * s6);
        if (tid == 0 && c + 3 < 16) {
            bar_wait(mb0 + 72 + 8 * s6, pE[s6]);
            pE[s6] ^= 1;
            issue6(c + 3);
        }
    }

    float* C = outv + (long)(z / HH) * ((long)LL * DD) + (z % HH) * 64;
    #pragma unroll
    for (int mt = 0; mt < 4; mt++) {
        const int rl = wm + mt * 16 + lm;
        const int rg = by * 128 + rl;
        const float i0 = 1.0f / rsum[(long)z * LL + rg];
        const float i1 = 1.0f / rsum[(long)z * LL + rg + 8];
        #pragma unroll
        for (int nt = 0; nt < 2; nt++) {
            const int cg = wn6 + nt * 8 + 2 * lk;
            *(float2*)&C[(long)rg * DD + cg] =
                make_float2(oacc[mt][nt][0] * i0, oacc[mt][nt][1] * i0);
            *(float2*)&C[(long)(rg + 8) * DD + cg] =
                make_float2(oacc[mt][nt][2] * i1, oacc[mt][nt][3] * i1);
        }
    }
}

// ---------------------------------------------------------------------------
// Fused pack kernel: input packing + rsum/cnt zeroing in one launch.
// ---------------------------------------------------------------------------
__device__ __forceinline__
void pack_x_dev(const float* __restrict__ x, __half* __restrict__ xp,
                int kx, int ly, int bz) {
    __half* blob = xp + (((long)bz * 8 + ly) * 12 + kx) * TH128;
    const float* src = x + ((long)(bz * LL + ly * 128)) * DD + kx * 64;
    #pragma unroll
    for (int i = 0; i < 8; i++) {
        const int s = threadIdx.x + i * 256;
        const int row = s >> 4, c4 = (s & 15) << 2;
        const float4 v = *(const float4*)&src[(long)row * DD + c4];
        *(__half2*)&blob[row * 72 + c4]     = __float22half2_rn(make_float2(v.x, v.y));
        *(__half2*)&blob[row * 72 + c4 + 2] = __float22half2_rn(make_float2(v.z, v.w));
    }
}
__device__ __forceinline__
void pack_qk_dev(const float* __restrict__ in, __half* __restrict__ op,
                 int kx, int xy, int hz) {
    __half* blob = op + (((long)hz * 6 + xy) * 12 + kx) * TH128;
    const float* src = in + ((long)hz * DD + kx * 64) * DD + xy * 128;
    #pragma unroll
    for (int i = 0; i < 8; i++) {
        const int s = threadIdx.x + i * 256;
        const int c = s >> 5, x0 = (s & 31) << 2;
        const float4 v = *(const float4*)&src[(long)c * DD + x0];
        blob[(x0 + 0) * 72 + c] = __float2half_rn(v.x);
        blob[(x0 + 1) * 72 + c] = __float2half_rn(v.y);
        blob[(x0 + 2) * 72 + c] = __float2half_rn(v.z);
        blob[(x0 + 3) * 72 + c] = __float2half_rn(v.w);
    }
}
__device__ __forceinline__
void pack_v_dev(const float* __restrict__ v, __half* __restrict__ vp,
                int kx, int hy) {
    __half* blob = vp + ((long)hy * 12 + kx) * TH64;
    const float* src = v + (long)hy * DHH * DD + kx * 64;
    #pragma unroll
    for (int i = 0; i < 4; i++) {
        const int s = threadIdx.x + i * 256;
        const int row = s >> 4, c4 = (s & 15) << 2;
        const float4 w = *(const float4*)&src[(long)row * DD + c4];
        *(__half2*)&blob[row * 72 + c4]     = __float22half2_rn(make_float2(w.x, w.y));
        *(__half2*)&blob[row * 72 + c4 + 2] = __float22half2_rn(make_float2(w.z, w.w));
    }
}

__global__ void pack_all(const float* __restrict__ x, const float* __restrict__ q,
                         const float* __restrict__ k, const float* __restrict__ v,
                         __half* __restrict__ xp, __half* __restrict__ qp,
                         __half* __restrict__ kp, __half* __restrict__ vp,
                         float* __restrict__ rsum, int* __restrict__ cnt)
{
    const int bid = blockIdx.x;
    if (bid < 384) {
        pack_x_dev(x, xp, bid % 12, (bid / 12) % 8, bid / 96);
    } else if (bid < 1248) {
        const int t = bid - 384;
        pack_qk_dev(q, qp, t % 12, (t / 12) % 6, t / 72);
    } else if (bid < 2112) {
        const int t = bid - 1248;
        pack_qk_dev(k, kp, t % 12, (t / 12) % 6, t / 72);
    } else if (bid < 2256) {
        const int t = bid - 2112;
        pack_v_dev(v, vp, t % 12, t / 12);
    } else {
        const int t = bid - 2256;                   // zero rsum (48 x 1024 floats)
        float4* dst = (float4*)&rsum[(long)t * LL];
        dst[threadIdx.x] = make_float4(0.f, 0.f, 0.f, 0.f);
        if (t == 0 && threadIdx.x < 192)            // zero cnt (384 ints)
            ((int2*)cnt)[threadIdx.x] = make_int2(0, 0);
    }
}

// ---------------------------------------------------------------------------
extern "C" void kernel_launch(void* const* d_in, const int* in_sizes, int n_in,
                              void* d_out, int out_size)
{
    const float* x = (const float*)d_in[0];
    const float* k = (const float*)d_in[1];
    const float* q = (const float*)d_in[2];
    const float* v = (const float*)d_in[3];
    float* out = (float*)d_out;

    __half *xp, *qp, *kp, *vp, *Mp, *Ap, *Sp, *Vtp;
    float* rs;
    int* cn;
    cudaGetSymbolAddress((void**)&xp, g_xp);
    cudaGetSymbolAddress((void**)&qp, g_qp);
    cudaGetSymbolAddress((void**)&kp, g_kp);
    cudaGetSymbolAddress((void**)&vp, g_vp);
    cudaGetSymbolAddress((void**)&Mp, g_Mp);
    cudaGetSymbolAddress((void**)&Ap, g_Ap);
    cudaGetSymbolAddress((void**)&Sp, g_Sp);
    cudaGetSymbolAddress((void**)&Vtp, g_Vtp);
    cudaGetSymbolAddress((void**)&rs, g_rsum);
    cudaGetSymbolAddress((void**)&cn, g_cnt);

    const int SM128 = 1024 + 3 * (18432 + 18432);   // 111616

    auto* G2 = gemm_k<1, 2, 128, 1, 0>;
    cudaFuncSetAttribute(gemm_g1g5, cudaFuncAttributeMaxDynamicSharedMemorySize, SM128);
    cudaFuncSetAttribute(G2, cudaFuncAttributeMaxDynamicSharedMemorySize, SM128);
    cudaFuncSetAttribute(gemm_g3f, cudaFuncAttributeMaxDynamicSharedMemorySize, SM128);

    // 0) pack inputs + zero rsum/cnt, one launch
    pack_all<<<dim3(2304), 256>>>(x, q, k, v, xp, qp, kp, vp, rs, cn);

    // 1+5) M^T = q^T k  and  Vt = x v^T, one launch
    gemm_g1g5<<<dim3(816), 256, SM128>>>(qp, kp, Mp, xp, vp, Vtp);

    // 2) A[l,e] = sum_d x[l,d] M^T[e,d]
    G2<<<dim3(6, 8, BB * HH), 256, SM128>>>(xp, Mp, Ap, 12, 12, 8L * 12 * TH128);

    // 3+6) P = exp(A x^T) + rsum; last block per (z,l-tile) computes
    //      out = (P . Vt) / rsum inline
    gemm_g3f<<<dim3(8, 8, BB * HH), 256, SM128>>>(Ap, xp, Sp, Vtp, rs, out, cn);
}

// round 17
// speedup vs baseline: 1.0322x; 1.0322x over previous
#include <cuda_runtime.h>
#include <cuda_fp16.h>
#include <cstdint>

#define BB 4
#define LL 1024
#define DD 768
#define HH 12
#define DHH 64

// Packed fp16 scratch: XM tiles, k-contiguous, k-chunks of 64.
//   128-row tile = 128 x 72 halfs (64 data + 8 pad) = 18432B
//   64-row tile  =  64 x 72 halfs = 9216B
#define TH128 9216
#define TH64  4608
__device__ __align__(1024) __half g_xp [(size_t)BB * 8 * 12 * TH128];
__device__ __align__(1024) __half g_qp [(size_t)HH * 6 * 12 * TH128];
__device__ __align__(1024) __half g_kp [(size_t)HH * 6 * 12 * TH128];
__device__ __align__(1024) __half g_vp [(size_t)HH * 12 * TH64];
__device__ __align__(1024) __half g_Mp [(size_t)HH * 6 * 12 * TH128];
__device__ __align__(1024) __half g_Ap [(size_t)BB * HH * 8 * 12 * TH128];
__device__ __align__(1024) __half g_Sp [(size_t)BB * HH * 8 * 16 * TH128]; // P = exp(S)
__device__ __align__(1024) __half g_Vtp[(size_t)BB * HH * 16 * TH64];
__device__ float g_rsum[(size_t)BB * HH * LL];       // per-row sums of exp(S)
__device__ int   g_cnt[(size_t)BB * HH * 8];         // per (z, l-tile) G2 completion

__device__ __forceinline__ void mma_f16(float* c, const unsigned* a, const unsigned* b) {
    asm volatile(
        "mma.sync.aligned.m16n8k16.row.col.f32.f16.f16.f32 "
        "{%0,%1,%2,%3}, {%4,%5,%6,%7}, {%8,%9}, {%0,%1,%2,%3};"
        : "+f"(c[0]), "+f"(c[1]), "+f"(c[2]), "+f"(c[3])
        : "r"(a[0]), "r"(a[1]), "r"(a[2]), "r"(a[3]), "r"(b[0]), "r"(b[1]));
}

__device__ __forceinline__ uint32_t sa32(const void* p) {
    return (uint32_t)__cvta_generic_to_shared(p);
}
__device__ __forceinline__ void bulk_g2s(uint32_t dst, const void* src,
                                         uint32_t bytes, uint32_t mbar) {
    asm volatile(
        "cp.async.bulk.shared::cluster.global.mbarrier::complete_tx::bytes [%0], [%1], %2, [%3];"
        :: "r"(dst), "l"(src), "r"(bytes), "r"(mbar) : "memory");
}
__device__ __forceinline__ void bar_wait(uint32_t mbar, unsigned parity) {
    asm volatile(
        "{\n\t.reg .pred P;\n\t"
        "W_%=:\n\t"
        "mbarrier.try_wait.parity.acquire.cta.shared::cta.b64 P, [%0], %1, 0x989680;\n\t"
        "@P bra D_%=;\n\t"
        "bra W_%=;\n\t"
        "D_%=:\n\t}"
        :: "r"(mbar), "r"(parity) : "memory");
}
#define MBAR_INIT(a, c) \
    asm volatile("mbarrier.init.shared.b64 [%0], %1;" :: "r"(a), "r"(c) : "memory")
#define MBAR_TX(a, b) \
    asm volatile("mbarrier.arrive.expect_tx.shared.b64 _, [%0], %1;" :: "r"(a), "r"(b) : "memory")
#define MBAR_ARRIVE(a) \
    asm volatile("mbarrier.arrive.release.cta.shared::cta.b64 _, [%0];" :: "r"(a) : "memory")

// ---------------------------------------------------------------------------
// Bulk-fed fp16 HMMA GEMM on packed XM tiles, 3-stage ring with per-warp
// empty barriers.  C[m,n] = sum_k A[m,k]*B[n,k].  Block 128 x BROWS x 64.
//  EPI: 0 plain fp32 (+(z%HH)*64 col offset); 1 fp16 XM tiles rows=m;
//       2 fp16 XM tiles rows=n (ETR rows/tile, transposed store)
//  EXS: epilogue stores exp(acc) + atomic per-row sums
//  SCL: epilogue scales acc by 1/rsum[row]
// ---------------------------------------------------------------------------
template<int AZ, int BZ, int BROWS, int EPI, int ETR, bool EXS, bool SCL>
__device__ __forceinline__
void gemm_dev(const __half* __restrict__ Apk, const __half* __restrict__ Bpk,
              void* __restrict__ Cg, float* __restrict__ rsum,
              int nkt, int cNK, long czs, long cs1, int ldc,
              int bx, int by, int bz, int gdx, int gdy, __half* smem)
{
    constexpr int BTH = BROWS * 72;
    constexpr uint32_t ABYT = TH128 * 2, BBYT = BTH * 2;
    constexpr int STAGE = TH128 + BTH;              // halfs per stage
    constexpr int NT = BROWS / 32;

    const uint32_t mb0 = sa32(&smem[0]);            // full[3] @ +0,8,16; empty[3] @ +24,32,40
    __half* tiles = smem + 512;

    const int z = bz;
    const long zA = (AZ == 1) ? z / HH : (AZ == 2 ? z % HH : z);
    const long zB = (BZ == 1) ? z / HH : (BZ == 2 ? z % HH : z);
    const __half* Abase = Apk + ((zA * gdy + by) * (long)nkt) * TH128;
    const __half* Bbase = Bpk + ((zB * gdx + bx) * (long)nkt) * BTH;

    const int tid = threadIdx.x;
    const int lane = tid & 31;
    const int wid = tid >> 5;
    const int wm = (wid & 1) * 64;
    const int wn = (wid >> 1) * (BROWS / 4);
    const int lm = lane >> 2;
    const int lk = lane & 3;
    const int m0 = by * 128;
    const int n0 = bx * BROWS;

    float acc[4][NT][4];
    #pragma unroll
    for (int i = 0; i < 4; i++)
        #pragma unroll
        for (int j = 0; j < NT; j++)
            #pragma unroll
            for (int r = 0; r < 4; r++) acc[i][j][r] = 0.f;

    if (tid == 0) {
        MBAR_INIT(mb0, 1);      MBAR_INIT(mb0 + 8, 1);  MBAR_INIT(mb0 + 16, 1);
        MBAR_INIT(mb0 + 24, 8); MBAR_INIT(mb0 + 32, 8); MBAR_INIT(mb0 + 40, 8);
    }
    __syncthreads();

    auto issue = [&](int st, int kt) {
        const uint32_t m = mb0 + 8 * st;
        MBAR_TX(m, ABYT + BBYT);
        bulk_g2s(sa32(tiles) + st * STAGE * 2, Abase + (long)kt * TH128, ABYT, m);
        bulk_g2s(sa32(tiles) + st * STAGE * 2 + ABYT, Bbase + (long)kt * BTH, BBYT, m);
    };
    if (tid == 0) { issue(0, 0); issue(1, 1); issue(2, 2); }

    auto compute = [&](int st) {
        const __half* __restrict__ Ab = tiles + st * STAGE;
        const __half* __restrict__ Bb = Ab + TH128;
        #pragma unroll
        for (int s = 0; s < 4; s++) {               // 4 x k16 per 64-k stage
            const int kb = s * 16 + 2 * lk;
            unsigned a[4][4], b[NT][2];
            #pragma unroll
            for (int mt = 0; mt < 4; mt++) {
                const int mr = wm + mt * 16 + lm;
                a[mt][0] = *(const unsigned*)&Ab[mr * 72 + kb];
                a[mt][1] = *(const unsigned*)&Ab[(mr + 8) * 72 + kb];
                a[mt][2] = *(const unsigned*)&Ab[mr * 72 + kb + 8];
                a[mt][3] = *(const unsigned*)&Ab[(mr + 8) * 72 + kb + 8];
            }
            #pragma unroll
            for (int nt = 0; nt < NT; nt++) {
                const int nc = wn + nt * 8 + lm;
                b[nt][0] = *(const unsigned*)&Bb[nc * 72 + kb];
                b[nt][1] = *(const unsigned*)&Bb[nc * 72 + kb + 8];
            }
            #pragma unroll
            for (int mt = 0; mt < 4; mt++)
                #pragma unroll
                for (int nt = 0; nt < NT; nt++)
                    mma_f16(acc[mt][nt], a[mt], b[nt]);
        }
    };

    unsigned phF[3] = {0, 0, 0};
    unsigned phE[3] = {0, 0, 0};
    int st = 0;
    for (int t = 0; t < nkt; t++) {
        bar_wait(mb0 + 8 * st, phF[st]);
        phF[st] ^= 1;
        compute(st);
        if (lane == 0) MBAR_ARRIVE(mb0 + 24 + 8 * st);     // warp done with stage
        if (tid == 0 && t + 3 < nkt) {
            bar_wait(mb0 + 24 + 8 * st, phE[st]);          // all 8 warps done
            phE[st] ^= 1;
            issue(st, t + 3);
        }
        st = (st == 2) ? 0 : st + 1;
    }

    // ---- epilogue ----
    #pragma unroll
    for (int mt = 0; mt < 4; mt++) {
        const int rl = wm + mt * 16 + lm;
        const int rg = m0 + rl;
        float s0 = 0.f, s1 = 0.f;
        float i0 = 1.f, i1 = 1.f;
        if (SCL) {
            i0 = 1.0f / rsum[(long)z * LL + rg];
            i1 = 1.0f / rsum[(long)z * LL + rg + 8];
        }
        #pragma unroll
        for (int nt = 0; nt < NT; nt++) {
            const int cl = wn + nt * 8 + 2 * lk;
            const int cg = n0 + cl;
            float v0 = acc[mt][nt][0], v1 = acc[mt][nt][1];
            float v2 = acc[mt][nt][2], v3 = acc[mt][nt][3];
            if (SCL) { v0 *= i0; v1 *= i0; v2 *= i1; v3 *= i1; }
            if (EPI == 0) {
                float* C = (float*)Cg + (long)(z / HH) * cs1 + (long)(z % HH) * 64;
                *(float2*)&C[(long)rg * ldc + cg]       = make_float2(v0, v1);
                *(float2*)&C[(long)(rg + 8) * ldc + cg] = make_float2(v2, v3);
            } else if (EPI == 1) {
                __half* zb = (__half*)Cg + (long)z * czs
                           + ((long)by * cNK + (cg >> 6)) * TH128;
                const int co = cl & 63;
                __half2 h01, h23;
                if (EXS) {
                    h01 = __float22half2_rn(make_float2(__expf(v0), __expf(v1)));
                    h23 = __float22half2_rn(make_float2(__expf(v2), __expf(v3)));
                    const float2 f01 = __half22float2(h01);
                    const float2 f23 = __half22float2(h23);
                    s0 += f01.x + f01.y;
                    s1 += f23.x + f23.y;
                } else {
                    h01 = __float22half2_rn(make_float2(v0, v1));
                    h23 = __float22half2_rn(make_float2(v2, v3));
                }
                *(__half2*)&zb[rl * 72 + co]       = h01;
                *(__half2*)&zb[(rl + 8) * 72 + co] = h23;
            } else {
                __half* zb = (__half*)Cg + (long)z * czs
                           + ((long)(cg / ETR) * cNK + (rg >> 6)) * (ETR * 72);
                const int rr = rg & 63;
                zb[(cg & (ETR - 1)) * 72 + rr]           = __float2half_rn(v0);
                zb[((cg + 1) & (ETR - 1)) * 72 + rr]     = __float2half_rn(v1);
                zb[(cg & (ETR - 1)) * 72 + rr + 8]       = __float2half_rn(v2);
                zb[((cg + 1) & (ETR - 1)) * 72 + rr + 8] = __float2half_rn(v3);
            }
        }
        if (EXS) {
            s0 += __shfl_xor_sync(~0u, s0, 1); s0 += __shfl_xor_sync(~0u, s0, 2);
            s1 += __shfl_xor_sync(~0u, s1, 1); s1 += __shfl_xor_sync(~0u, s1, 2);
            if (lk == 0) {
                atomicAdd(&rsum[(long)z * LL + rg], s0);
                atomicAdd(&rsum[(long)z * LL + rg + 8], s1);
            }
        }
    }
}

// ---- standalone GEMM kernel (G6) ------------------------------------------
template<int AZ, int BZ, int BROWS, int EPI, int ETR, bool EXS, bool SCL>
__global__ __launch_bounds__(256, 2)
void gemm_k(const __half* __restrict__ Apk, const __half* __restrict__ Bpk,
            void* __restrict__ Cg, float* __restrict__ rsum,
            int nkt, int cNK, long czs, long cs1, int ldc)
{
    extern __shared__ __align__(16) __half smem[];
    gemm_dev<AZ, BZ, BROWS, EPI, ETR, EXS, SCL>(
        Apk, Bpk, Cg, rsum, nkt, cNK, czs, cs1, ldc,
        blockIdx.x, blockIdx.y, blockIdx.z, gridDim.x, gridDim.y, smem);
}

// ---- fused G1 (M^T = q^T k) + G5 (Vt = x v^T) in one launch ---------------
__global__ __launch_bounds__(256, 2)
void gemm_g1g5(const __half* __restrict__ qp, const __half* __restrict__ kp,
               __half* __restrict__ Mp,
               const __half* __restrict__ xp, const __half* __restrict__ vp,
               __half* __restrict__ Vtp)
{
    extern __shared__ __align__(16) __half smem[];
    const int bid = blockIdx.x;
    if (bid < 432) {                                // G1: grid (6,6,12)
        gemm_dev<0, 0, 128, 2, 128, false, false>(
            qp, kp, Mp, nullptr, 12, 12, 6L * 12 * TH128, 0, 0,
            bid % 6, (bid / 6) % 6, bid / 36, 6, 6, smem);
    } else {                                        // G5: grid (1,8,48)
        const int t = bid - 432;
        gemm_dev<1, 2, 64, 2, 64, false, false>(
            xp, vp, Vtp, nullptr, 12, 16, 16L * TH64, 0, 0,
            0, t % 8, t / 8, 1, 8, smem);
    }
}

// ---- chained G2 + G3 in ONE launch ----------------------------------------
// bids [0,2304): G2 tile (bx=bid%6, by=(bid/6)%8, z=bid/48); after its
//   epilogue, fence + atomicAdd cnt[z*8+by].
// bids [2304,5376): G3 tile (bx=t%8, by=(t/8)%8, z=t/64); spin-waits until
//   cnt[z*8+by]==6 (its A panel complete), then runs.
// Deadlock-free under monotonic block dispatch: any resident G3 block implies
// all G2 blocks (lower bids) are resident-or-retired, and G2 never waits.
__global__ __launch_bounds__(256, 2)
void gemm_g2g3(const __half* __restrict__ xp, const __half* __restrict__ Mp,
               __half* __restrict__ Ap, __half* __restrict__ Sp,
               float* __restrict__ rsum, int* __restrict__ cnt)
{
    extern __shared__ __align__(16) __half smem[];
    const int bid = blockIdx.x;
    if (bid < 2304) {                               // ---- G2 ----
        const int bx = bid % 6, by = (bid / 6) % 8, z = bid / 48;
        gemm_dev<1, 2, 128, 1, 0, false, false>(
            xp, Mp, Ap, nullptr, 12, 12, 8L * 12 * TH128, 0, 0,
            bx, by, z, 6, 8, smem);
        __syncthreads();
        if (threadIdx.x == 0) {
            __threadfence();
            atomicAdd(&cnt[z * 8 + by], 1);
        }
    } else {                                        // ---- G3 ----
        const int t = bid - 2304;
        const int bx = t % 8, by = (t / 8) % 8, z = t / 64;
        if (threadIdx.x == 0) {
            volatile int* c = &cnt[z * 8 + by];
            while (*c < 6) __nanosleep(64);
            __threadfence();
        }
        __syncthreads();
        gemm_dev<0, 1, 128, 1, 0, true, false>(
            Ap, xp, Sp, rsum, 12, 16, 8L * 16 * TH128, 0, 0,
            bx, by, z, 8, 8, smem);
    }
}

// ---------------------------------------------------------------------------
// Fused pack kernel: input packing + rsum/cnt zeroing in one launch.
// ---------------------------------------------------------------------------
__device__ __forceinline__
void pack_x_dev(const float* __restrict__ x, __half* __restrict__ xp,
                int kx, int ly, int bz) {
    __half* blob = xp + (((long)bz * 8 + ly) * 12 + kx) * TH128;
    const float* src = x + ((long)(bz * LL + ly * 128)) * DD + kx * 64;
    #pragma unroll
    for (int i = 0; i < 8; i++) {
        const int s = threadIdx.x + i * 256;
        const int row = s >> 4, c4 = (s & 15) << 2;
        const float4 v = *(const float4*)&src[(long)row * DD + c4];
        *(__half2*)&blob[row * 72 + c4]     = __float22half2_rn(make_float2(v.x, v.y));
        *(__half2*)&blob[row * 72 + c4 + 2] = __float22half2_rn(make_float2(v.z, v.w));
    }
}
__device__ __forceinline__
void pack_qk_dev(const float* __restrict__ in, __half* __restrict__ op,
                 int kx, int xy, int hz) {
    __half* blob = op + (((long)hz * 6 + xy) * 12 + kx) * TH128;
    const float* src = in + ((long)hz * DD + kx * 64) * DD + xy * 128;
    #pragma unroll
    for (int i = 0; i < 8; i++) {
        const int s = threadIdx.x + i * 256;
        const int c = s >> 5, x0 = (s & 31) << 2;
        const float4 v = *(const float4*)&src[(long)c * DD + x0];
        blob[(x0 + 0) * 72 + c] = __float2half_rn(v.x);
        blob[(x0 + 1) * 72 + c] = __float2half_rn(v.y);
        blob[(x0 + 2) * 72 + c] = __float2half_rn(v.z);
        blob[(x0 + 3) * 72 + c] = __float2half_rn(v.w);
    }
}
__device__ __forceinline__
void pack_v_dev(const float* __restrict__ v, __half* __restrict__ vp,
                int kx, int hy) {
    __half* blob = vp + ((long)hy * 12 + kx) * TH64;
    const float* src = v + (long)hy * DHH * DD + kx * 64;
    #pragma unroll
    for (int i = 0; i < 4; i++) {
        const int s = threadIdx.x + i * 256;
        const int row = s >> 4, c4 = (s & 15) << 2;
        const float4 w = *(const float4*)&src[(long)row * DD + c4];
        *(__half2*)&blob[row * 72 + c4]     = __float22half2_rn(make_float2(w.x, w.y));
        *(__half2*)&blob[row * 72 + c4 + 2] = __float22half2_rn(make_float2(w.z, w.w));
    }
}

__global__ void pack_all(const float* __restrict__ x, const float* __restrict__ q,
                         const float* __restrict__ k, const float* __restrict__ v,
                         __half* __restrict__ xp, __half* __restrict__ qp,
                         __half* __restrict__ kp, __half* __restrict__ vp,
                         float* __restrict__ rsum, int* __restrict__ cnt)
{
    const int bid = blockIdx.x;
    if (bid < 384) {
        pack_x_dev(x, xp, bid % 12, (bid / 12) % 8, bid / 96);
    } else if (bid < 1248) {
        const int t = bid - 384;
        pack_qk_dev(q, qp, t % 12, (t / 12) % 6, t / 72);
    } else if (bid < 2112) {
        const int t = bid - 1248;
        pack_qk_dev(k, kp, t % 12, (t / 12) % 6, t / 72);
    } else if (bid < 2256) {
        const int t = bid - 2112;
        pack_v_dev(v, vp, t % 12, t / 12);
    } else {
        const int t = bid - 2256;                   // zero rsum (48 x 1024 floats)
        float4* dst = (float4*)&rsum[(long)t * LL];
        dst[threadIdx.x] = make_float4(0.f, 0.f, 0.f, 0.f);
        if (t == 0 && threadIdx.x < 192)            // zero cnt (384 ints)
            ((int2*)cnt)[threadIdx.x] = make_int2(0, 0);
    }
}

// ---------------------------------------------------------------------------
extern "C" void kernel_launch(void* const* d_in, const int* in_sizes, int n_in,
                              void* d_out, int out_size)
{
    const float* x = (const float*)d_in[0];
    const float* k = (const float*)d_in[1];
    const float* q = (const float*)d_in[2];
    const float* v = (const float*)d_in[3];
    float* out = (float*)d_out;

    __half *xp, *qp, *kp, *vp, *Mp, *Ap, *Sp, *Vtp;
    float* rs;
    int* cn;
    cudaGetSymbolAddress((void**)&xp, g_xp);
    cudaGetSymbolAddress((void**)&qp, g_qp);
    cudaGetSymbolAddress((void**)&kp, g_kp);
    cudaGetSymbolAddress((void**)&vp, g_vp);
    cudaGetSymbolAddress((void**)&Mp, g_Mp);
    cudaGetSymbolAddress((void**)&Ap, g_Ap);
    cudaGetSymbolAddress((void**)&Sp, g_Sp);
    cudaGetSymbolAddress((void**)&Vtp, g_Vtp);
    cudaGetSymbolAddress((void**)&rs, g_rsum);
    cudaGetSymbolAddress((void**)&cn, g_cnt);

    const int SM128 = 1024 + 3 * (18432 + 18432);   // 111616
    const int SM64  = 1024 + 3 * (18432 + 9216);    // 83968

    auto* G6 = gemm_k<0, 0, 64, 0, 0, false, true>;
    cudaFuncSetAttribute(gemm_g1g5, cudaFuncAttributeMaxDynamicSharedMemorySize, SM128);
    cudaFuncSetAttribute(gemm_g2g3, cudaFuncAttributeMaxDynamicSharedMemorySize, SM128);
    cudaFuncSetAttribute(G6, cudaFuncAttributeMaxDynamicSharedMemorySize, SM64);

    // 0) pack inputs + zero rsum/cnt, one launch
    pack_all<<<dim3(2304), 256>>>(x, q, k, v, xp, qp, kp, vp, rs, cn);

    // 1+5) M^T = q^T k  and  Vt = x v^T, one launch
    gemm_g1g5<<<dim3(816), 256, SM128>>>(qp, kp, Mp, xp, vp, Vtp);

    // 2+3) chained: G2 (A = x M^T) then counter-gated G3 (P = exp(A x^T) + rsum)
    gemm_g2g3<<<dim3(5376), 256, SM128>>>(xp, Mp, Ap, Sp, rs, cn);

    // 6) out[l, h*64+j] = (sum_m P[l,m] Vt[j,m]) / rsum[l]
    G6<<<dim3(1, 8, BB * HH), 256, SM64>>>(Sp, Vtp, out, rs, 16, 0, 0, (long)LL * DD, DD);
}